// round 1
// baseline (speedup 1.0000x reference)
#include <cuda_runtime.h>
#include <math.h>

// Problem constants
#define Nn 32
#define Cc 64
#define Tt 300
#define Vv 25
#define Mm 2
#define Oo 64
#define Ss 3
#define SO 192          // S*O rows of conv_w
#define TTile 6         // T-tile per block (300 = 50*6)
#define TVC (TTile*Vv)  // 150 columns per tile
#define SXS 152         // padded stride for sx/sy
#define SYS 152
#define SWS 193         // padded stride for transposed W (conflict-free)
#define THREADS 256

// Shared memory layout (floats):
//   sx   [64][152]      x tile (also residual source)
//   sy   [192][152]     conv output y (includes bias)
//   sW   [64][193]      W transposed: sW[c][so] = conv_w[so*64+c]
//   sPA  [3*25*25]
//   sbias[192], sscale[64], sshift[64]
#define SM_FLOATS (Cc*SXS + SO*SYS + Cc*SWS + Ss*Vv*Vv + SO + Oo + Oo)

__global__ __launch_bounds__(THREADS, 1)
void stgcn_fused_kernel(const float* __restrict__ x,
                        const float* __restrict__ PA,
                        const float* __restrict__ Wc,
                        const float* __restrict__ bc,
                        const float* __restrict__ gamma,
                        const float* __restrict__ beta,
                        const float* __restrict__ mean,
                        const float* __restrict__ var,
                        float* __restrict__ out)
{
    extern __shared__ float sm[];
    float* sx     = sm;                      // 64*152
    float* sy     = sx + Cc*SXS;             // 192*152
    float* sW     = sy + SO*SYS;             // 64*193
    float* sPA    = sW + Cc*SWS;             // 1875
    float* sbias  = sPA + Ss*Vv*Vv;          // 192
    float* sscale = sbias + SO;              // 64
    float* sshift = sscale + Oo;             // 64

    const int tid  = threadIdx.x;
    const int bid  = blockIdx.x;
    const int b    = bid & 63;               // batch index (n*2+m), fastest
    const int tile = bid >> 6;
    const int n    = b >> 1;
    const int m    = b & 1;
    const int t0   = tile * TTile;

    // ---- cooperative loads ----
    for (int i = tid; i < Ss*Vv*Vv; i += THREADS) sPA[i] = PA[i];
    for (int i = tid; i < SO; i += THREADS)       sbias[i] = bc[i];
    if (tid < Oo) {
        float sc = gamma[tid] * rsqrtf(var[tid] + 1e-5f);
        sscale[tid] = sc;
        sshift[tid] = beta[tid] - mean[tid] * sc;
    }
    // W transpose into smem: sW[c][so] = conv_w[so][c]; padded stride kills conflicts
    for (int i = tid; i < SO*Cc; i += THREADS) {
        int so = i >> 6;
        int c  = i & 63;
        sW[c*SWS + so] = Wc[i];
    }
    // x tile: gather (stride-2 in global due to M-last layout)
    for (int i = tid; i < Cc*TVC; i += THREADS) {
        int c  = i / TVC;
        int tv = i - c*TVC;
        int t  = tv / Vv;
        int v  = tv - t*Vv;
        sx[c*SXS + tv] = x[ (((n*Cc + c)*Tt + (t0+t))*Vv + v)*Mm + m ];
    }
    __syncthreads();

    // ---- Stage A: conv GEMM  y[so][tv] = bias[so] + sum_c W[so][c]*x[c][tv] ----
    // outputs 192x150, register tile 6(so) x 5(tv); 32x30 = 960 tasks
    for (int task = tid; task < 960; task += THREADS) {
        int sog = task / 30, tvg = task - sog*30;
        int so0 = sog*6,     tv0 = tvg*5;
        float acc[6][5];
        #pragma unroll
        for (int i = 0; i < 6; i++) {
            float bv = sbias[so0+i];
            #pragma unroll
            for (int j = 0; j < 5; j++) acc[i][j] = bv;
        }
        const float* wp = sW + so0;
        const float* xp = sx + tv0;
        #pragma unroll 4
        for (int c = 0; c < Cc; c++) {
            float wr[6], xr[5];
            #pragma unroll
            for (int i = 0; i < 6; i++) wr[i] = wp[c*SWS + i];
            #pragma unroll
            for (int j = 0; j < 5; j++) xr[j] = xp[c*SXS + j];
            #pragma unroll
            for (int i = 0; i < 6; i++)
                #pragma unroll
                for (int j = 0; j < 5; j++)
                    acc[i][j] = fmaf(wr[i], xr[j], acc[i][j]);
        }
        #pragma unroll
        for (int i = 0; i < 6; i++)
            #pragma unroll
            for (int j = 0; j < 5; j++)
                sy[(so0+i)*SYS + tv0 + j] = acc[i][j];
    }
    __syncthreads();

    // ---- Stage B: adjacency + BN + relu + residual + relu + store ----
    // z[o][t][w] = sum_s sum_v PA[s][v][w] * y[s*64+o][t*25+v]
    // outputs 64x150, register tile 2(o) x 5(w) at fixed t; 32*6*5 = 960 tasks
    for (int task = tid; task < 960; task += THREADS) {
        int og  = task / 30;
        int rem = task - og*30;
        int t   = rem / 5;
        int wg  = rem - t*5;
        int o0  = og*2;
        int w0  = wg*5;

        float acc[2][5];
        #pragma unroll
        for (int r = 0; r < 2; r++)
            #pragma unroll
            for (int j = 0; j < 5; j++) acc[r][j] = 0.f;

        #pragma unroll
        for (int s = 0; s < Ss; s++) {
            const float* pap = sPA + s*(Vv*Vv) + w0;
            const float* yp  = sy + (s*Oo + o0)*SYS + t*Vv;
            #pragma unroll 5
            for (int v = 0; v < Vv; v++) {
                float pr[5];
                #pragma unroll
                for (int j = 0; j < 5; j++) pr[j] = pap[v*Vv + j];
                float y0 = yp[v];
                float y1 = yp[SYS + v];
                #pragma unroll
                for (int j = 0; j < 5; j++) {
                    acc[0][j] = fmaf(y0, pr[j], acc[0][j]);
                    acc[1][j] = fmaf(y1, pr[j], acc[1][j]);
                }
            }
        }

        // epilogue: BN (inference) + relu, add identity residual, relu, store
        #pragma unroll
        for (int r = 0; r < 2; r++) {
            int o = o0 + r;
            float sc = sscale[o];
            float sh = sshift[o];
            #pragma unroll
            for (int j = 0; j < 5; j++) {
                int w = w0 + j;
                float z = fmaf(acc[r][j], sc, sh);
                z = fmaxf(z, 0.f);
                float res = sx[o*SXS + t*Vv + w];
                float val = fmaxf(z + res, 0.f);
                out[ (((n*Oo + o)*Tt + (t0+t))*Vv + w)*Mm + m ] = val;
            }
        }
    }
}

extern "C" void kernel_launch(void* const* d_in, const int* in_sizes, int n_in,
                              void* d_out, int out_size)
{
    const float* x     = (const float*)d_in[0];
    const float* PA    = (const float*)d_in[1];
    const float* Wc    = (const float*)d_in[2];
    const float* bc    = (const float*)d_in[3];
    const float* gamma = (const float*)d_in[4];
    const float* beta  = (const float*)d_in[5];
    const float* mean  = (const float*)d_in[6];
    const float* var   = (const float*)d_in[7];
    float* out = (float*)d_out;

    const int smem_bytes = SM_FLOATS * (int)sizeof(float);  // ~213.8 KB
    cudaFuncSetAttribute(stgcn_fused_kernel,
                         cudaFuncAttributeMaxDynamicSharedMemorySize, smem_bytes);

    dim3 grid(64 * (Tt / TTile));   // 64 batches * 50 T-tiles = 3200
    stgcn_fused_kernel<<<grid, THREADS, smem_bytes>>>(
        x, PA, Wc, bc, gamma, beta, mean, var, out);
}